// round 9
// baseline (speedup 1.0000x reference)
#include <cuda_runtime.h>
#include <cstdint>

// ---------------------------------------------------------------------------
// Skeletonize — bit-packed implementation, partitionable-threefry RNG.
//   padded grid: (2, 162, 162, 162); bit-packed along z: 3 x u64 per (b,X,Y) row
//   RNG: JAX threefry_partitionable: counter (0, flat_index), bits = o0 ^ o1
// ---------------------------------------------------------------------------

#define NPAD 162
#define ROWS_PER_BATCH (162*162)        // 26244
#define NROWS (2*ROWS_PER_BATCH)        // 52488
#define WPR 3                           // u64 words per row (192 bits, 162 used)
#define HALF 4251528u                   // 162^3 (batch stride in flat index)

__device__ unsigned long long g_img[NROWS*WPR];
__device__ unsigned long long g_end[NROWS*WPR];

__device__ __forceinline__ uint32_t rotl32(uint32_t x, int r){ return (x<<r)|(x>>(32-r)); }

// JAX threefry2x32 with key (0, 42)
__device__ __forceinline__ uint32_t threefry_xor(uint32_t x0, uint32_t x1){
  const uint32_t ks1 = 42u;
  const uint32_t ks2 = 0x1BD11BDAu ^ 42u;
  x0 += 0u; x1 += ks1;
#define TF_RND(r) { x0 += x1; x1 = rotl32(x1, (r)); x1 ^= x0; }
  TF_RND(13) TF_RND(15) TF_RND(26) TF_RND(6)
  x0 += ks1; x1 += ks2 + 1u;
  TF_RND(17) TF_RND(29) TF_RND(16) TF_RND(24)
  x0 += ks2; x1 += 2u;
  TF_RND(13) TF_RND(15) TF_RND(26) TF_RND(6)
  x0 += 0u;  x1 += ks1 + 3u;
  TF_RND(17) TF_RND(29) TF_RND(16) TF_RND(24)
  x0 += ks1; x1 += ks2 + 4u;
  TF_RND(13) TF_RND(15) TF_RND(26) TF_RND(6)
  x0 += ks2; x1 += 5u;
#undef TF_RND
  return x0 ^ x1;      // partitionable combine for <=32-bit draws
}

// Elementwise chain matching XLA (no FMA contraction). hard <=> z > 0.
__device__ __forceinline__ int hard_bit(uint32_t bits, float img){
  float f = __fadd_rn(__uint_as_float((bits >> 9) | 0x3f800000u), -1.0f);
  float u = __fadd_rn(__fmul_rn(f, 1.0f), 1e-8f);   // span (1-2e-8) rounds to 1.0f
  u = fmaxf(1e-8f, u);
  float noise = __fadd_rn(logf(u), -log1pf(-u));
  float alpha = __fdiv_rn(__fadd_rn(img, 1e-8f),
                          __fadd_rn(__fadd_rn(1.0f, -img), 1e-8f));
  float zv = __fadd_rn(logf(alpha), __fmul_rn(noise, 0.33f));
  return zv > 0.0f;
}

__global__ void k_binarize(const float* __restrict__ in){
  int gt = blockIdx.x*blockDim.x + threadIdx.x;
  int W = gt >> 5;
  int lane = gt & 31;
  if (W >= ROWS_PER_BATCH*6) return;
  int r0 = W / 6, k = W % 6;
  int X = r0 / NPAD, Y = r0 % NPAD;
  int z = k*32 + lane;
  bool valid = (z < NPAD);
  uint32_t i = (uint32_t)r0 * (uint32_t)NPAD + (uint32_t)(valid ? z : 0);
  uint32_t b0bits = threefry_xor(0u, i);          // batch 0: counter (0, i)
  uint32_t b1bits = threefry_xor(0u, i + HALF);   // batch 1: counter (0, i+HALF)
  bool interior = valid && X>=1 && X<=160 && Y>=1 && Y<=160 && z>=1 && z<=160;
  float v0 = 0.f, v1 = 0.f;
  if (interior){
    int ui = ((X-1)*160 + (Y-1))*160 + (z-1);
    v0 = in[ui];
    v1 = in[ui + 160*160*160];
  }
  int h0 = hard_bit(b0bits, v0);   // pad voxels (img=0) produce 0
  int h1 = hard_bit(b1bits, v1);
  uint32_t m0 = __ballot_sync(0xFFFFFFFFu, valid && h0);
  uint32_t m1 = __ballot_sync(0xFFFFFFFFu, valid && h1);
  if (lane == 0){
    uint32_t* p = (uint32_t*)g_img;
    p[(size_t)r0*6 + k] = m0;                       // batch 0
    p[(size_t)(ROWS_PER_BATCH + r0)*6 + k] = m1;    // batch 1
  }
}

// saturating {0,1,>=2} bit-sliced counter
#define SAT(one, ge, x) { unsigned long long _x=(x); (ge) |= (one) & _x; (one) |= _x; }

__global__ void k_endpoint(){
  int t = blockIdx.x*blockDim.x + threadIdx.x;
  if (t >= NROWS*WPR) return;
  int w = t % 3; int r = t / 3;
  int Y = r % NPAD; int rX = r / NPAD; int X = rX % NPAD; int b = rX / NPAD;
  unsigned long long one=0, ge=0;
  #pragma unroll
  for (int i=0;i<3;i++){
    #pragma unroll
    for (int j=0;j<3;j++){
      int XX = X + i - 1, YY = Y + j - 1;
      bool ok = (XX>=0 && XX<NPAD && YY>=0 && YY<NPAD);
      const unsigned long long* row = g_img + (size_t)((b*NPAD + XX)*NPAD + YY)*WPR;
      unsigned long long wm = (ok && w>0) ? row[w-1] : 0ull;
      unsigned long long wc =  ok         ? row[w]   : 0ull;
      unsigned long long wp = (ok && w<2) ? row[w+1] : 0ull;
      unsigned long long M = (wc<<1) | (wm>>63);
      unsigned long long P = (wc>>1) | (wp<<63);
      SAT(one, ge, M);
      if (!(i==1 && j==1)) SAT(one, ge, wc);   // exclude center voxel
      SAT(one, ge, P);
    }
  }
  g_end[t] = ~ge;   // bit=1  <=>  n26 <= 1  (endpoint)
}

__global__ void k_simple(int xo, int yo, int zo){
  int t = blockIdx.x*blockDim.x + threadIdx.x;
  if (t >= 2*81*81*3) return;
  int w = t % 3; int q = t/3;
  int Yi = q % 81; q /= 81;
  int Xi = q % 81; int b = q / 81;
  int X = xo + 2*Xi, Y = yo + 2*Yi;

  unsigned long long A[3][3][3];
  #pragma unroll
  for (int i=0;i<3;i++){
    #pragma unroll
    for (int j=0;j<3;j++){
      int XX = X + i - 1, YY = Y + j - 1;
      bool ok = (XX>=0 && XX<NPAD && YY>=0 && YY<NPAD);
      const unsigned long long* row = g_img + (size_t)((b*NPAD + XX)*NPAD + YY)*WPR;
      unsigned long long wm = (ok && w>0) ? row[w-1] : 0ull;
      unsigned long long wc =  ok         ? row[w]   : 0ull;
      unsigned long long wp = (ok && w<2) ? row[w+1] : 0ull;
      A[i][j][0] = (wc<<1) | (wm>>63);
      A[i][j][1] = wc;
      A[i][j][2] = (wc>>1) | (wp<<63);
    }
  }

  // n18 (faces+edges), then extend with corners for n26
  unsigned long long one18=0, ge18=0;
  #pragma unroll
  for (int i=0;i<3;i++){
    #pragma unroll
    for (int j=0;j<3;j++){
      #pragma unroll
      for (int k=0;k<3;k++){
        int c = (i==1?0:1)+(j==1?0:1)+(k==1?0:1);
        if (c==1 || c==2) SAT(one18, ge18, A[i][j][k]);
      }
    }
  }
  unsigned long long one26=one18, ge26=ge18;
  #pragma unroll
  for (int i=0;i<3;i+=2){
    #pragma unroll
    for (int j=0;j<3;j+=2){
      #pragma unroll
      for (int k=0;k<3;k+=2) SAT(one26, ge26, A[i][j][k]);
    }
  }
  // n6 counts BACKGROUND face neighbors
  unsigned long long one6=0, ge6=0;
  SAT(one6, ge6, ~A[0][1][1]); SAT(one6, ge6, ~A[2][1][1]);
  SAT(one6, ge6, ~A[1][0][1]); SAT(one6, ge6, ~A[1][2][1]);
  SAT(one6, ge6, ~A[1][1][0]); SAT(one6, ge6, ~A[1][1][2]);

  // b26 octants: corner fg AND its 3 faces + 3 edges all bg
  unsigned long long anyB = 0;
  #pragma unroll
  for (int i=0;i<3;i+=2){
    #pragma unroll
    for (int j=0;j<3;j+=2){
      #pragma unroll
      for (int k=0;k<3;k+=2){
        unsigned long long others = A[i][1][1] | A[1][j][1] | A[1][1][k]
                                  | A[i][j][1] | A[i][1][k] | A[1][j][k];
        anyB |= A[i][j][k] & ~others;
      }
    }
  }
  // a6: face bg AND its 4 coplanar edge neighbors fg, 6 directions
  unsigned long long anyA = 0;
  #pragma unroll
  for (int s=0;s<3;s+=2){
    anyA |= ~A[s][1][1] & A[s][0][1] & A[s][2][1] & A[s][1][0] & A[s][1][2];
    anyA |= ~A[1][s][1] & A[0][s][1] & A[2][s][1] & A[1][s][0] & A[1][s][2];
    anyA |= ~A[1][1][s] & A[0][1][s] & A[2][1][s] & A[1][0][s] & A[1][2][s];
  }

  unsigned long long notB = ~anyB;
  unsigned long long simple = (one6 & ~ge6)            // n6 == 1
                            | (one26 & ~ge26)          // n26 == 1
                            | (one18 & ~ge18 & notB)   // n18 == 1 && no b26
                            | (ge6 & ~anyA & notB);    // n6 >= 2 && no a6 && no b26
  unsigned long long zmask;
  {
    // center parity: bits at z = zo mod 2 within this word (word base 64w is even)
    zmask = (zo==0) ? 0x5555555555555555ull : 0xAAAAAAAAAAAAAAAAull;
  }
  size_t idx = (size_t)((b*NPAD + X)*NPAD + Y)*WPR + w;
  unsigned long long del = simple & ~g_end[idx] & zmask;
  g_img[idx] &= ~del;
}

__global__ void k_unpack(float* __restrict__ out){
  int t = blockIdx.x*blockDim.x + threadIdx.x;
  if (t >= 2*160*160*160) return;
  int z = t % 160; int q = t/160;
  int y = q % 160; q /= 160;
  int x = q % 160; int b = q / 160;
  int zz = z + 1;
  size_t row = (size_t)((b*NPAD + (x+1))*NPAD + (y+1));
  unsigned long long wv = g_img[row*WPR + (zz>>6)];
  out[t] = (float)((wv >> (zz & 63)) & 1ull);
}

extern "C" void kernel_launch(void* const* d_in, const int* in_sizes, int n_in,
                              void* d_out, int out_size){
  const float* in = (const float*)d_in[0];
  float* out = (float*)d_out;
  (void)in_sizes; (void)n_in; (void)out_size;

  // binarize: 26244*6 = 157464 warps -> 5,038,848 threads
  k_binarize<<<19683, 256>>>(in);

  static const int OFF[8][3] = {{0,0,0},{1,0,0},{0,1,0},{1,1,0},
                                {0,0,1},{1,0,1},{0,1,1},{1,1,1}};
  const int nword = NROWS*WPR;              // 157464
  const int nsub  = 2*81*81*3;              // 39366
  for (int it = 0; it < 5; ++it){
    k_endpoint<<<(nword+255)/256, 256>>>();
    for (int o = 0; o < 8; ++o)
      k_simple<<<(nsub+127)/128, 128>>>(OFF[o][0], OFF[o][1], OFF[o][2]);
  }

  k_unpack<<<(2*160*160*160 + 255)/256, 256>>>(out);
}